// round 13
// baseline (speedup 1.0000x reference)
#include <cuda_runtime.h>
#include <cuda_fp16.h>
#include <cstdint>

#define B_SZ 32
#define T_SZ 2048
#define DIN  1024
#define HID  2048
#define BM   128
#define BN   256
#define BK   64          // fp16 elements per K-chunk (128B rows -> SW128)
#define NCHUNK (DIN / BK)

// ---------------- device-global scratch (allocation-free) ----------------
__device__ __align__(16) __half g_h16 [(size_t)B_SZ * T_SZ * DIN];  // 128 MB
__device__ __align__(16) __half g_w116[(size_t)HID * DIN];           // 4 MB
__device__ float g_part[(size_t)16 * B_SZ * HID];                    // 4 MB [tt][b][n]
__device__ float g_red[B_SZ * 8 * 2];                                // slice partials

// ---------------- helpers ----------------
__device__ __forceinline__ uint32_t smem_u32(const void* p) {
    uint32_t a;
    asm("{ .reg .u64 t; cvta.to.shared.u64 t, %1; cvt.u32.u64 %0, t; }" : "=r"(a) : "l"(p));
    return a;
}
__device__ __forceinline__ void ldsm_x4(uint32_t& r0, uint32_t& r1, uint32_t& r2, uint32_t& r3,
                                        uint32_t addr) {
    asm volatile("ldmatrix.sync.aligned.m8n8.x4.shared.b16 {%0,%1,%2,%3}, [%4];"
                 : "=r"(r0), "=r"(r1), "=r"(r2), "=r"(r3) : "r"(addr));
}
__device__ __forceinline__ void mma_f16(float* c, const uint32_t* a, const uint32_t* b) {
    asm volatile(
        "mma.sync.aligned.m16n8k16.row.col.f32.f16.f16.f32 "
        "{%0,%1,%2,%3}, {%4,%5,%6,%7}, {%8,%9}, {%0,%1,%2,%3};"
        : "+f"(c[0]), "+f"(c[1]), "+f"(c[2]), "+f"(c[3])
        : "r"(a[0]), "r"(a[1]), "r"(a[2]), "r"(a[3]), "r"(b[0]), "r"(b[1]));
}
#define CP_ASYNC16(dst, src) \
    asm volatile("cp.async.cg.shared.global [%0], [%1], 16;" :: "r"(dst), "l"(src))
#define CP_COMMIT() asm volatile("cp.async.commit_group;" ::: "memory")
#define CP_WAIT2()  asm volatile("cp.async.wait_group 2;" ::: "memory")

// ---------------- conversion kernels (fp32 -> fp16 RNE) ----------------
__global__ void __launch_bounds__(256) cvt_h_kernel(const float4* __restrict__ src,
                                                    const int* __restrict__ tl) {
    unsigned g0 = (blockIdx.x * 256u + threadIdx.x) * 2u;   // 2 groups of 8 floats
#pragma unroll
    for (int it = 0; it < 2; it++) {
        unsigned g = g0 + it;
        unsigned b = g >> 18;
        unsigned t = (g >> 7) & (T_SZ - 1);
        int len = tl[b];
        unsigned tmax = ((unsigned)len + 127u) & ~127u;
        if (t >= tmax) continue;
        float4 a = src[(size_t)g * 2], c = src[(size_t)g * 2 + 1];
        __half2 r0 = __floats2half2_rn(a.x, a.y);
        __half2 r1 = __floats2half2_rn(a.z, a.w);
        __half2 r2 = __floats2half2_rn(c.x, c.y);
        __half2 r3 = __floats2half2_rn(c.z, c.w);
        uint4 u;
        u.x = *reinterpret_cast<uint32_t*>(&r0);
        u.y = *reinterpret_cast<uint32_t*>(&r1);
        u.z = *reinterpret_cast<uint32_t*>(&r2);
        u.w = *reinterpret_cast<uint32_t*>(&r3);
        reinterpret_cast<uint4*>(g_h16)[g] = u;
    }
}

__global__ void __launch_bounds__(256) cvt_w1_kernel(const float4* __restrict__ src) {
    unsigned g = blockIdx.x * 256u + threadIdx.x;
    float4 a = src[(size_t)g * 2], c = src[(size_t)g * 2 + 1];
    __half2 r0 = __floats2half2_rn(a.x, a.y);
    __half2 r1 = __floats2half2_rn(a.z, a.w);
    __half2 r2 = __floats2half2_rn(c.x, c.y);
    __half2 r3 = __floats2half2_rn(c.z, c.w);
    uint4 u;
    u.x = *reinterpret_cast<uint32_t*>(&r0);
    u.y = *reinterpret_cast<uint32_t*>(&r1);
    u.z = *reinterpret_cast<uint32_t*>(&r2);
    u.w = *reinterpret_cast<uint32_t*>(&r3);
    reinterpret_cast<uint4*>(g_w116)[g] = u;
}

// ---------------- chunk loaders (SW128 swizzle, 128B rows) ----------------
// A: 128 rows x 64 fp16 = 16KB ; B: 256 rows x 64 fp16 = 32KB
__device__ __forceinline__ void load_chunk(uint32_t smA, uint32_t smB,
                                           const __half* gA, const __half* gB,
                                           int k0, int tid) {
#pragma unroll
    for (int j = 0; j < 4; j++) {          // A: 1024 segs of 16B
        int idx = tid + j * 256;
        int row = idx >> 3, seg = idx & 7;
        uint32_t sw = (uint32_t)(row * 128) + (((uint32_t)seg * 16) ^ (((uint32_t)row & 7) << 4));
        CP_ASYNC16(smA + sw, (const char*)(gA + (size_t)row * DIN + k0) + seg * 16);
    }
#pragma unroll
    for (int j = 0; j < 8; j++) {          // B: 2048 segs of 16B
        int idx = tid + j * 256;
        int row = idx >> 3, seg = idx & 7;
        uint32_t sw = (uint32_t)(row * 128) + (((uint32_t)seg * 16) ^ (((uint32_t)row & 7) << 4));
        CP_ASYNC16(smB + sw, (const char*)(gB + (size_t)row * DIN + k0) + seg * 16);
    }
}

// ---------------- SMEM layout ----------------
#define SM_B1   0        // 256 floats (1KB)
#define SM_PART 1024     // 2 x 256 floats (2KB)
#define SM_BUFA 4096     // 3 stages x 16KB = 48KB
#define SM_BUFB 53248    // 3 stages x 32KB = 96KB
#define SMEM_TOTAL 151552

// ---------------- fused GEMM tile (relu(h@W1^T+b1)) + column partial sums ----------------
// grid: (8 nt, 16 tt, 32 b); 256 threads; warps 2(M)x4(N), warp tile 64x64.
// Square warp tiles: SMEM re-reads A x4 + B x2 = 128KB/chunk over 2048 tensor cyc = 50%
// crossbar (vs 75% at 32x64). fp16 operands, fp32 accumulate, R6-proven pipeline.
__global__ void __launch_bounds__(256, 1) gemm_kernel(const int* __restrict__ tl,
                                                      const float* __restrict__ b1) {
    const int nt = blockIdx.x, tt = blockIdx.y, b = blockIdx.z;
    const int len = tl[b];
    if (tt * BM >= len) return;

    extern __shared__ char smem[];
    float* sb1  = (float*)(smem + SM_B1);
    float* part = (float*)(smem + SM_PART);
    const uint32_t sbase = smem_u32(smem);
    const uint32_t smA = sbase + SM_BUFA;
    const uint32_t smB = sbase + SM_BUFB;

    const int tid = threadIdx.x, lane = tid & 31, wid = tid >> 5;
    const int wm = wid >> 2, wn = wid & 3;     // 2 x 4 warp grid

    sb1[tid] = b1[nt * BN + tid];

    const __half* gA = g_h16  + ((size_t)b * T_SZ + (size_t)tt * BM) * DIN;
    const __half* gB = g_w116 + (size_t)nt * BN * DIN;

    float acc[4][8][4];                        // 4 m16 x 8 n8 x 4
#pragma unroll
    for (int i = 0; i < 4; i++)
#pragma unroll
        for (int j = 0; j < 8; j++)
#pragma unroll
            for (int k = 0; k < 4; k++) acc[i][j][k] = 0.f;

    const int r8  = lane & 7;
    const int mi  = lane >> 3;
    const uint32_t rot = (uint32_t)r8 << 4;
    const uint32_t akx = (uint32_t)(mi >> 1) * 16;   // A: mats 2,3 -> k+8
    const uint32_t bkx = (uint32_t)(mi & 1) * 16;    // B: mats 1,3 -> k+8
    uint32_t aRow[4], bRow[4];
#pragma unroll
    for (int mt = 0; mt < 4; mt++)
        aRow[mt] = (uint32_t)((wm * 64 + mt * 16 + (mi & 1) * 8 + r8) * 128);
#pragma unroll
    for (int p = 0; p < 4; p++)
        bRow[p] = (uint32_t)((wn * 64 + p * 16 + (mi >> 1) * 8 + r8) * 128);

    load_chunk(smA, smB, gA, gB, 0, tid);
    CP_COMMIT();
    load_chunk(smA + 16384, smB + 32768, gA, gB, BK, tid);
    CP_COMMIT();

    for (int c = 0; c < NCHUNK; c++) {
        if (c + 2 < NCHUNK)
            load_chunk(smA + ((c + 2) % 3) * 16384, smB + ((c + 2) % 3) * 32768,
                       gA, gB, (c + 2) * BK, tid);
        CP_COMMIT();
        CP_WAIT2();
        __syncthreads();

        const uint32_t bufA = smA + (c % 3) * 16384;
        const uint32_t bufB = smB + (c % 3) * 32768;
#pragma unroll
        for (int ks = 0; ks < 4; ks++) {
            const uint32_t kb = (uint32_t)ks * 32;
            uint32_t a[4][4];
#pragma unroll
            for (int mt = 0; mt < 4; mt++)
                ldsm_x4(a[mt][0], a[mt][1], a[mt][2], a[mt][3],
                        bufA + aRow[mt] + ((kb + akx) ^ rot));
#pragma unroll
            for (int p = 0; p < 4; p++) {
                uint32_t q0, q1, q2, q3;
                ldsm_x4(q0, q1, q2, q3, bufB + bRow[p] + ((kb + bkx) ^ rot));
                uint32_t bfa[2] = { q0, q1 };
                uint32_t bfb[2] = { q2, q3 };
#pragma unroll
                for (int mt = 0; mt < 4; mt++) {
                    mma_f16(acc[mt][2 * p],     a[mt], bfa);
                    mma_f16(acc[mt][2 * p + 1], a[mt], bfb);
                }
            }
        }
        __syncthreads();
    }

    // ---- epilogue: bias + relu + row mask + deterministic column reduce ----
    const int r0g = tt * BM + wm * 64 + (lane >> 2);
#pragma unroll
    for (int n8 = 0; n8 < 8; n8++) {
        const int c0 = wn * 64 + n8 * 8 + (lane & 3) * 2;
        const float bias0 = sb1[c0], bias1 = sb1[c0 + 1];
        float s0 = 0.f, s1 = 0.f;
#pragma unroll
        for (int mt = 0; mt < 4; mt++) {
            const int rr = r0g + mt * 16;
            if (rr < len) {
                s0 += fmaxf(acc[mt][n8][0] + bias0, 0.f);
                s1 += fmaxf(acc[mt][n8][1] + bias1, 0.f);
            }
            if (rr + 8 < len) {
                s0 += fmaxf(acc[mt][n8][2] + bias0, 0.f);
                s1 += fmaxf(acc[mt][n8][3] + bias1, 0.f);
            }
        }
#pragma unroll
        for (int o = 4; o < 32; o <<= 1) {
            s0 += __shfl_xor_sync(0xffffffffu, s0, o);
            s1 += __shfl_xor_sync(0xffffffffu, s1, o);
        }
        if (lane < 4) {
            part[wm * 256 + c0] = s0;
            part[wm * 256 + c0 + 1] = s1;
        }
    }
    __syncthreads();
    {
        float v = part[tid] + part[256 + tid];
        g_part[((size_t)tt * B_SZ + b) * HID + nt * BN + tid] = v;
    }
}

// ---------------- tail stage 1: per-(batch, 256-col slice) pool + W2 dot ----------------
__global__ void __launch_bounds__(256) pool_dot_kernel(const int* __restrict__ tl,
                                                       const float* __restrict__ W2) {
    __shared__ float red[16];
    const int b = blockIdx.x, sl = blockIdx.y;
    const int tid = threadIdx.x, lane = tid & 31, wid = tid >> 5;
    const int len = tl[b];
    const int ntt = (len + BM - 1) >> 7;
    const float inv = 1.f / (float)len;
    const int hcol = sl * 256 + tid;

    float s = 0.f;
    for (int t = 0; t < ntt; t++)
        s += g_part[((size_t)t * B_SZ + b) * HID + hcol];
    float v = s * inv;
    float s0 = v * W2[hcol];
    float s1 = v * W2[HID + hcol];
#pragma unroll
    for (int o = 16; o > 0; o >>= 1) {
        s0 += __shfl_xor_sync(0xffffffffu, s0, o);
        s1 += __shfl_xor_sync(0xffffffffu, s1, o);
    }
    if (lane == 0) { red[wid * 2] = s0; red[wid * 2 + 1] = s1; }
    __syncthreads();
    if (tid < 2) {
        float t = 0.f;
#pragma unroll
        for (int w = 0; w < 8; w++) t += red[w * 2 + tid];
        g_red[(b * 8 + sl) * 2 + tid] = t;
    }
}

// ---------------- tail stage 2: fold 8 slices per (b, tag), add bias ----------------
__global__ void __launch_bounds__(64) score_final_kernel(const float* __restrict__ b2,
                                                         float* __restrict__ out) {
    int idx = threadIdx.x;
    int b = idx >> 1, tag = idx & 1;
    float s = 0.f;
#pragma unroll
    for (int sl = 0; sl < 8; sl++) s += g_red[(b * 8 + sl) * 2 + tag];
    out[b * 2 + tag] = s + b2[tag];
}

// ---------------- launch ----------------
extern "C" void kernel_launch(void* const* d_in, const int* in_sizes, int n_in,
                              void* d_out, int out_size) {
    const float* h  = (const float*)d_in[0];
    const int*   tl = (const int*)d_in[1];
    const float* W1 = (const float*)d_in[2];
    const float* b1 = (const float*)d_in[3];
    const float* W2 = (const float*)d_in[4];
    const float* b2 = (const float*)d_in[5];
    float* out = (float*)d_out;

    static bool attr_set = false;
    if (!attr_set) {
        cudaFuncSetAttribute(gemm_kernel,
                             cudaFuncAttributeMaxDynamicSharedMemorySize, SMEM_TOTAL);
        attr_set = true;
    }

    cvt_h_kernel<<<(B_SZ * T_SZ * DIN / 16) / 256, 256>>>((const float4*)h, tl);
    cvt_w1_kernel<<<(HID * DIN / 8) / 256, 256>>>((const float4*)W1);
    gemm_kernel<<<dim3(HID / BN, T_SZ / BM, B_SZ), 256, SMEM_TOTAL>>>(tl, b1);
    pool_dot_kernel<<<dim3(B_SZ, 8), 256>>>(tl, W2);
    score_final_kernel<<<1, 64>>>(b2, out);
}

// round 15
// speedup vs baseline: 1.1070x; 1.1070x over previous
#include <cuda_runtime.h>
#include <cuda_fp16.h>
#include <cstdint>

#define B_SZ 32
#define T_SZ 2048
#define DIN  1024
#define HID  2048
#define BM   128
#define BN   128
#define BK   64
#define NCHUNK (DIN / BK)

// ---------------- device-global scratch (allocation-free) ----------------
__device__ __align__(16) __half g_h16 [(size_t)B_SZ * T_SZ * DIN];  // 128 MB
__device__ __align__(16) __half g_w116[(size_t)HID * DIN];           // 4 MB
__device__ float g_part[(size_t)16 * B_SZ * HID];                    // 4 MB [tt][b][n]
__device__ float g_red[B_SZ * 8 * 2];

// ---------------- helpers ----------------
__device__ __forceinline__ uint32_t smem_u32(const void* p) {
    uint32_t a;
    asm("{ .reg .u64 t; cvta.to.shared.u64 t, %1; cvt.u32.u64 %0, t; }" : "=r"(a) : "l"(p));
    return a;
}
__device__ __forceinline__ void ldsm_x4(uint32_t& r0, uint32_t& r1, uint32_t& r2, uint32_t& r3,
                                        uint32_t addr) {
    asm volatile("ldmatrix.sync.aligned.m8n8.x4.shared.b16 {%0,%1,%2,%3}, [%4];"
                 : "=r"(r0), "=r"(r1), "=r"(r2), "=r"(r3) : "r"(addr));
}
__device__ __forceinline__ void mma_f16(float* c, const uint32_t* a, const uint32_t* b) {
    asm volatile(
        "mma.sync.aligned.m16n8k16.row.col.f32.f16.f16.f32 "
        "{%0,%1,%2,%3}, {%4,%5,%6,%7}, {%8,%9}, {%0,%1,%2,%3};"
        : "+f"(c[0]), "+f"(c[1]), "+f"(c[2]), "+f"(c[3])
        : "r"(a[0]), "r"(a[1]), "r"(a[2]), "r"(a[3]), "r"(b[0]), "r"(b[1]));
}
#define CP_ASYNC16(dst, src) \
    asm volatile("cp.async.cg.shared.global [%0], [%1], 16;" :: "r"(dst), "l"(src))
#define CP_COMMIT() asm volatile("cp.async.commit_group;" ::: "memory")
#define CP_WAIT2()  asm volatile("cp.async.wait_group 2;" ::: "memory")

// ---------------- conversion kernels (fp32 -> fp16 RNE) ----------------
__global__ void __launch_bounds__(256) cvt_h_kernel(const float4* __restrict__ src,
                                                    const int* __restrict__ tl) {
    unsigned g0 = (blockIdx.x * 256u + threadIdx.x) * 2u;
#pragma unroll
    for (int it = 0; it < 2; it++) {
        unsigned g = g0 + it;
        unsigned b = g >> 18;
        unsigned t = (g >> 7) & (T_SZ - 1);
        int len = tl[b];
        unsigned tmax = ((unsigned)len + 127u) & ~127u;
        if (t >= tmax) continue;
        float4 a = src[(size_t)g * 2], c = src[(size_t)g * 2 + 1];
        __half2 r0 = __floats2half2_rn(a.x, a.y);
        __half2 r1 = __floats2half2_rn(a.z, a.w);
        __half2 r2 = __floats2half2_rn(c.x, c.y);
        __half2 r3 = __floats2half2_rn(c.z, c.w);
        uint4 u;
        u.x = *reinterpret_cast<uint32_t*>(&r0);
        u.y = *reinterpret_cast<uint32_t*>(&r1);
        u.z = *reinterpret_cast<uint32_t*>(&r2);
        u.w = *reinterpret_cast<uint32_t*>(&r3);
        reinterpret_cast<uint4*>(g_h16)[g] = u;
    }
}

__global__ void __launch_bounds__(256) cvt_w1_kernel(const float4* __restrict__ src) {
    unsigned g = blockIdx.x * 256u + threadIdx.x;
    float4 a = src[(size_t)g * 2], c = src[(size_t)g * 2 + 1];
    __half2 r0 = __floats2half2_rn(a.x, a.y);
    __half2 r1 = __floats2half2_rn(a.z, a.w);
    __half2 r2 = __floats2half2_rn(c.x, c.y);
    __half2 r3 = __floats2half2_rn(c.z, c.w);
    uint4 u;
    u.x = *reinterpret_cast<uint32_t*>(&r0);
    u.y = *reinterpret_cast<uint32_t*>(&r1);
    u.z = *reinterpret_cast<uint32_t*>(&r2);
    u.w = *reinterpret_cast<uint32_t*>(&r3);
    reinterpret_cast<uint4*>(g_w116)[g] = u;
}

// ---------------- chunk loader: 128 rows x 64 fp16 per tile, SW128, 128 threads ----------------
__device__ __forceinline__ void load_chunk(uint32_t smA, uint32_t smB,
                                           const __half* gA, const __half* gB,
                                           int k0, int tid) {
#pragma unroll
    for (int j = 0; j < 8; j++) {
        int idx = tid + j * 128;
        int row = idx >> 3, seg = idx & 7;
        uint32_t sw = (uint32_t)(row * 128) + (((uint32_t)seg * 16) ^ (((uint32_t)row & 7) << 4));
        CP_ASYNC16(smA + sw, (const char*)(gA + (size_t)row * DIN + k0) + seg * 16);
    }
#pragma unroll
    for (int j = 0; j < 8; j++) {
        int idx = tid + j * 128;
        int row = idx >> 3, seg = idx & 7;
        uint32_t sw = (uint32_t)(row * 128) + (((uint32_t)seg * 16) ^ (((uint32_t)row & 7) << 4));
        CP_ASYNC16(smB + sw, (const char*)(gB + (size_t)row * DIN + k0) + seg * 16);
    }
}

// ---------------- SMEM layout ----------------
#define SM_B1   0        // 128 floats (512B)
#define SM_PART 512      // 2 x 128 floats (1KB)
#define SM_BUFA 4096     // 3 stages x 16KB
#define SM_BUFB 53248    // 3 stages x 16KB
#define SMEM_TOTAL 102400

// ---------------- fused GEMM tile (relu(h@W1^T+b1)) + column partial sums ----------------
// grid: (16 nt, 16 tt, 32 b); 128 threads; warps 2(M)x2(N), warp tile 64x64.
// 2 CTAs/SM preserved. Per SM per chunk: SMEM = 2x(64KB ldsm + 32KB cp.async) = 192KB
// = 1500 cyc vs 2048 tensor cyc -> crossbar 73% (was ~98% at 32x64 warp tiles).
__global__ void __launch_bounds__(128, 2) gemm_kernel(const int* __restrict__ tl,
                                                      const float* __restrict__ b1) {
    const int nt = blockIdx.x, tt = blockIdx.y, b = blockIdx.z;
    const int len = tl[b];
    if (tt * BM >= len) return;

    extern __shared__ char smem[];
    float* sb1  = (float*)(smem + SM_B1);
    float* part = (float*)(smem + SM_PART);
    const uint32_t sbase = smem_u32(smem);
    const uint32_t smA = sbase + SM_BUFA;
    const uint32_t smB = sbase + SM_BUFB;

    const int tid = threadIdx.x, lane = tid & 31, wid = tid >> 5;
    const int wm = wid >> 1, wn = wid & 1;     // 2 x 2 warp grid

    sb1[tid] = b1[nt * BN + tid];

    const __half* gA = g_h16  + ((size_t)b * T_SZ + (size_t)tt * BM) * DIN;
    const __half* gB = g_w116 + (size_t)nt * BN * DIN;

    float acc[4][8][4];                        // 4 m16 x 8 n8
#pragma unroll
    for (int i = 0; i < 4; i++)
#pragma unroll
        for (int j = 0; j < 8; j++)
#pragma unroll
            for (int k = 0; k < 4; k++) acc[i][j][k] = 0.f;

    const int r8  = lane & 7;
    const int mi  = lane >> 3;
    const uint32_t rot = (uint32_t)r8 << 4;
    const uint32_t akx = (uint32_t)(mi >> 1) * 16;   // A: mats 2,3 -> k+8
    const uint32_t bkx = (uint32_t)(mi & 1) * 16;    // B: mats 1,3 -> k+8
    uint32_t aRow[4], bRow[4];
#pragma unroll
    for (int mt = 0; mt < 4; mt++)
        aRow[mt] = (uint32_t)((wm * 64 + mt * 16 + (mi & 1) * 8 + r8) * 128);
#pragma unroll
    for (int p = 0; p < 4; p++)
        bRow[p] = (uint32_t)((wn * 64 + p * 16 + (mi >> 1) * 8 + r8) * 128);

    load_chunk(smA, smB, gA, gB, 0, tid);
    CP_COMMIT();
    load_chunk(smA + 16384, smB + 16384, gA, gB, BK, tid);
    CP_COMMIT();

    for (int c = 0; c < NCHUNK; c++) {
        if (c + 2 < NCHUNK)
            load_chunk(smA + ((c + 2) % 3) * 16384, smB + ((c + 2) % 3) * 16384,
                       gA, gB, (c + 2) * BK, tid);
        CP_COMMIT();
        CP_WAIT2();
        __syncthreads();

        const uint32_t bufA = smA + (c % 3) * 16384;
        const uint32_t bufB = smB + (c % 3) * 16384;
#pragma unroll
        for (int ks = 0; ks < 4; ks++) {
            const uint32_t kb = (uint32_t)ks * 32;
            uint32_t a[4][4];
#pragma unroll
            for (int mt = 0; mt < 4; mt++)
                ldsm_x4(a[mt][0], a[mt][1], a[mt][2], a[mt][3],
                        bufA + aRow[mt] + ((kb + akx) ^ rot));
#pragma unroll
            for (int p = 0; p < 4; p++) {
                uint32_t q0, q1, q2, q3;
                ldsm_x4(q0, q1, q2, q3, bufB + bRow[p] + ((kb + bkx) ^ rot));
                uint32_t bfa[2] = { q0, q1 };
                uint32_t bfb[2] = { q2, q3 };
#pragma unroll
                for (int mt = 0; mt < 4; mt++) {
                    mma_f16(acc[mt][2 * p],     a[mt], bfa);
                    mma_f16(acc[mt][2 * p + 1], a[mt], bfb);
                }
            }
        }
        __syncthreads();
    }

    // ---- epilogue: bias + relu + row mask + deterministic column reduce ----
    const int r0g = tt * BM + wm * 64 + (lane >> 2);
#pragma unroll
    for (int n8 = 0; n8 < 8; n8++) {
        const int c0 = wn * 64 + n8 * 8 + (lane & 3) * 2;
        const float bias0 = sb1[c0], bias1 = sb1[c0 + 1];
        float s0 = 0.f, s1 = 0.f;
#pragma unroll
        for (int mt = 0; mt < 4; mt++) {
            const int rr = r0g + mt * 16;
            if (rr < len) {
                s0 += fmaxf(acc[mt][n8][0] + bias0, 0.f);
                s1 += fmaxf(acc[mt][n8][1] + bias1, 0.f);
            }
            if (rr + 8 < len) {
                s0 += fmaxf(acc[mt][n8][2] + bias0, 0.f);
                s1 += fmaxf(acc[mt][n8][3] + bias1, 0.f);
            }
        }
#pragma unroll
        for (int o = 4; o < 32; o <<= 1) {
            s0 += __shfl_xor_sync(0xffffffffu, s0, o);
            s1 += __shfl_xor_sync(0xffffffffu, s1, o);
        }
        if (lane < 4) {
            part[wm * 128 + c0] = s0;
            part[wm * 128 + c0 + 1] = s1;
        }
    }
    __syncthreads();
    {
        float v = part[tid] + part[128 + tid];
        g_part[((size_t)tt * B_SZ + b) * HID + nt * BN + tid] = v;
    }
}

// ---------------- tail stage 1: per-(batch, 256-col slice) pool + W2 dot ----------------
__global__ void __launch_bounds__(256) pool_dot_kernel(const int* __restrict__ tl,
                                                       const float* __restrict__ W2) {
    __shared__ float red[16];
    const int b = blockIdx.x, sl = blockIdx.y;
    const int tid = threadIdx.x, lane = tid & 31, wid = tid >> 5;
    const int len = tl[b];
    const int ntt = (len + BM - 1) >> 7;
    const float inv = 1.f / (float)len;
    const int hcol = sl * 256 + tid;

    float s = 0.f;
    for (int t = 0; t < ntt; t++)
        s += g_part[((size_t)t * B_SZ + b) * HID + hcol];
    float v = s * inv;
    float s0 = v * W2[hcol];
    float s1 = v * W2[HID + hcol];
#pragma unroll
    for (int o = 16; o > 0; o >>= 1) {
        s0 += __shfl_xor_sync(0xffffffffu, s0, o);
        s1 += __shfl_xor_sync(0xffffffffu, s1, o);
    }
    if (lane == 0) { red[wid * 2] = s0; red[wid * 2 + 1] = s1; }
    __syncthreads();
    if (tid < 2) {
        float t = 0.f;
#pragma unroll
        for (int w = 0; w < 8; w++) t += red[w * 2 + tid];
        g_red[(b * 8 + sl) * 2 + tid] = t;
    }
}

__global__ void __launch_bounds__(64) score_final_kernel(const float* __restrict__ b2,
                                                         float* __restrict__ out) {
    int idx = threadIdx.x;
    int b = idx >> 1, tag = idx & 1;
    float s = 0.f;
#pragma unroll
    for (int sl = 0; sl < 8; sl++) s += g_red[(b * 8 + sl) * 2 + tag];
    out[b * 2 + tag] = s + b2[tag];
}

// ---------------- launch (flat single stream) ----------------
extern "C" void kernel_launch(void* const* d_in, const int* in_sizes, int n_in,
                              void* d_out, int out_size) {
    const float* h  = (const float*)d_in[0];
    const int*   tl = (const int*)d_in[1];
    const float* W1 = (const float*)d_in[2];
    const float* b1 = (const float*)d_in[3];
    const float* W2 = (const float*)d_in[4];
    const float* b2 = (const float*)d_in[5];
    float* out = (float*)d_out;

    static bool attr_set = false;
    if (!attr_set) {
        cudaFuncSetAttribute(gemm_kernel,
                             cudaFuncAttributeMaxDynamicSharedMemorySize, SMEM_TOTAL);
        attr_set = true;
    }

    cvt_h_kernel<<<(B_SZ * T_SZ * DIN / 16) / 256, 256>>>((const float4*)h, tl);
    cvt_w1_kernel<<<(HID * DIN / 8) / 256, 256>>>((const float4*)W1);
    gemm_kernel<<<dim3(HID / BN, T_SZ / BM, B_SZ), 128, SMEM_TOTAL>>>(tl, b1);
    pool_dot_kernel<<<dim3(B_SZ, 8), 256>>>(tl, W2);
    score_final_kernel<<<1, 64>>>(b2, out);
}